// round 16
// baseline (speedup 1.0000x reference)
#include <cuda_runtime.h>
#include <math.h>

// out[n,j] = (x[n]==0 ? 0 : W[x[n],j]) + pe(n+1, j)
// pe(pos,j): even j -> cos(pos*w_{j/2}); odd j -> sin(pos*w_{(j+1)/2}); w_m = 1e-4^(m/512)
//
// R15: FOUR column passes (256 cols each), __stcs evict-first stores, plain __ldg
// gathers. Single change vs R14 (2 passes, 192us): pass granularity. Mechanism:
// per-pass table drops 103MB -> 51.5MB, leaving ~75MB L2 slack for the in-transit
// store stream, so the table stays resident in steady state (R14's 67us-isolated vs
// 96us-timed gap = capacity pressure). R13 already showed 4 passes are fast in
// isolation (36us/pass); its regression was the __stwt write-through stores
// (broke L2 write-combining), which stay reverted here.
// Numerics identical to R11/R12/R14 -> rel_err must stay 2.179366e-4.

#define DHID 1024
#define TPB 64             // one float4 per thread across the 256-col quarter
#define ROWS_PER_CTA 32
#define UNROLL 4
#define ANGLE_T 25000.0f

__global__ __launch_bounds__(TPB)
void pe_embed_q_kernel(const int* __restrict__ x,
                       const float4* __restrict__ W4,
                       float4* __restrict__ out4,
                       int N, int colq0)
{
    const int tl   = threadIdx.x;          // 0..63 within the quarter
    const int t    = colq0 + tl;           // global float4 index (0..255)
    const int lane = tl & 31;
    const long long row0 = (long long)blockIdx.x * ROWS_PER_CTA;
    if (row0 >= N) return;
    const long long rend = (row0 + ROWS_PER_CTA < (long long)N) ? row0 + ROWS_PER_CTA
                                                                : (long long)N;

    const float base   = 1.0f / 10000.0f;
    const float inv512 = 1.0f / 512.0f;
    const float w0 = powf(base, (float)(2 * t    ) * inv512);
    const float w1 = powf(base, (float)(2 * t + 1) * inv512);
    const float w2 = powf(base, (float)(2 * t + 2) * inv512);

    const float wmax  = __shfl_sync(0xFFFFFFFFu, w0, 0);
    const bool  exact = ((float)rend * wmax) > ANGLE_T;
    const bool  full  = ((rend - row0) % UNROLL) == 0;

    if (exact) {
        if (full) {
            int idx[UNROLL];
            #pragma unroll
            for (int k = 0; k < UNROLL; ++k) idx[k] = __ldg(&x[row0 + k]);

            for (long long n = row0; n < rend; n += UNROLL) {
                float4 e[UNROLL];
                #pragma unroll
                for (int k = 0; k < UNROLL; ++k) {
                    e[k] = make_float4(0.f, 0.f, 0.f, 0.f);
                    if (idx[k] != 0)
                        e[k] = __ldg(&W4[(long long)idx[k] * (DHID / 4) + t]);
                }
                if (n + UNROLL < rend) {
                    #pragma unroll
                    for (int k = 0; k < UNROLL; ++k) idx[k] = __ldg(&x[n + UNROLL + k]);
                }
                #pragma unroll
                for (int k = 0; k < UNROLL; ++k) {
                    const float pos = (float)(n + k + 1);
                    float sA, cA, sB, cB;
                    sincosf(pos * w1, &sA, &cA);
                    sincosf(pos * w2, &sB, &cB);
                    float c0 = __shfl_up_sync(0xFFFFFFFFu, cB, 1);
                    if (lane == 0) c0 = cosf(pos * w0);
                    float4 o;
                    o.x = e[k].x + c0;
                    o.y = e[k].y + sA;
                    o.z = e[k].z + cA;
                    o.w = e[k].w + sB;
                    __stcs(&out4[(n + k) * (DHID / 4) + t], o);
                }
            }
        } else {
            for (long long n = row0; n < rend; ++n) {
                const float pos = (float)(n + 1);
                float sA, cA, sB, cB;
                sincosf(pos * w1, &sA, &cA);
                sincosf(pos * w2, &sB, &cB);
                float c0 = __shfl_up_sync(0xFFFFFFFFu, cB, 1);
                if (lane == 0) c0 = cosf(pos * w0);
                const int idx = __ldg(&x[n]);
                float4 e = make_float4(0.f, 0.f, 0.f, 0.f);
                if (idx != 0) e = __ldg(&W4[(long long)idx * (DHID / 4) + t]);
                float4 o;
                o.x = e.x + c0; o.y = e.y + sA; o.z = e.z + cA; o.w = e.w + sB;
                __stcs(&out4[n * (DHID / 4) + t], o);
            }
        }
    } else {
        const float pos0 = (float)(row0 + 1);
        float s0, c0, s1, c1, s2, c2;
        sincosf(pos0 * w0, &s0, &c0);
        sincosf(pos0 * w1, &s1, &c1);
        sincosf(pos0 * w2, &s2, &c2);
        float sw0, cw0, sw1, cw1, sw2, cw2;
        sincosf(w0, &sw0, &cw0);
        sincosf(w1, &sw1, &cw1);
        sincosf(w2, &sw2, &cw2);

        if (full) {
            int idx[UNROLL];
            #pragma unroll
            for (int k = 0; k < UNROLL; ++k) idx[k] = __ldg(&x[row0 + k]);

            for (long long n = row0; n < rend; n += UNROLL) {
                float4 e[UNROLL];
                #pragma unroll
                for (int k = 0; k < UNROLL; ++k) {
                    e[k] = make_float4(0.f, 0.f, 0.f, 0.f);
                    if (idx[k] != 0)
                        e[k] = __ldg(&W4[(long long)idx[k] * (DHID / 4) + t]);
                }
                if (n + UNROLL < rend) {
                    #pragma unroll
                    for (int k = 0; k < UNROLL; ++k) idx[k] = __ldg(&x[n + UNROLL + k]);
                }
                #pragma unroll
                for (int k = 0; k < UNROLL; ++k) {
                    float4 o;
                    o.x = e[k].x + c0;
                    o.y = e[k].y + s1;
                    o.z = e[k].z + c1;
                    o.w = e[k].w + s2;
                    __stcs(&out4[(n + k) * (DHID / 4) + t], o);

                    float ns0 = fmaf(s0, cw0,  c0 * sw0);
                    float nc0 = fmaf(c0, cw0, -s0 * sw0);
                    float ns1 = fmaf(s1, cw1,  c1 * sw1);
                    float nc1 = fmaf(c1, cw1, -s1 * sw1);
                    float ns2 = fmaf(s2, cw2,  c2 * sw2);
                    float nc2 = fmaf(c2, cw2, -s2 * sw2);
                    s0 = ns0; c0 = nc0;
                    s1 = ns1; c1 = nc1;
                    s2 = ns2; c2 = nc2;
                }
            }
        } else {
            for (long long n = row0; n < rend; ++n) {
                const int idx = __ldg(&x[n]);
                float4 e = make_float4(0.f, 0.f, 0.f, 0.f);
                if (idx != 0) e = __ldg(&W4[(long long)idx * (DHID / 4) + t]);
                float4 o;
                o.x = e.x + c0; o.y = e.y + s1; o.z = e.z + c1; o.w = e.w + s2;
                __stcs(&out4[n * (DHID / 4) + t], o);

                float ns0 = fmaf(s0, cw0,  c0 * sw0);
                float nc0 = fmaf(c0, cw0, -s0 * sw0);
                float ns1 = fmaf(s1, cw1,  c1 * sw1);
                float nc1 = fmaf(c1, cw1, -s1 * sw1);
                float ns2 = fmaf(s2, cw2,  c2 * sw2);
                float nc2 = fmaf(c2, cw2, -s2 * sw2);
                s0 = ns0; c0 = nc0;
                s1 = ns1; c1 = nc1;
                s2 = ns2; c2 = nc2;
            }
        }
    }
}

extern "C" void kernel_launch(void* const* d_in, const int* in_sizes, int n_in,
                              void* d_out, int out_size)
{
    const int*   x   = (const int*)d_in[0];    // int32 [N]
    const float* W   = (const float*)d_in[1];  // f32 [V,1024]
    float*       out = (float*)d_out;          // f32 [N,1024]
    const int N = in_sizes[0];

    const int grid = (N + ROWS_PER_CTA - 1) / ROWS_PER_CTA;
    // Four sequential passes; each pass's 51.5MB quarter of W is L2-resident.
    pe_embed_q_kernel<<<grid, TPB>>>(x, (const float4*)W, (float4*)out, N, 0);
    pe_embed_q_kernel<<<grid, TPB>>>(x, (const float4*)W, (float4*)out, N, 64);
    pe_embed_q_kernel<<<grid, TPB>>>(x, (const float4*)W, (float4*)out, N, 128);
    pe_embed_q_kernel<<<grid, TPB>>>(x, (const float4*)W, (float4*)out, N, 192);
}